// round 3
// baseline (speedup 1.0000x reference)
#include <cuda_runtime.h>
#include <cuda_fp16.h>

#define IMG      384
#define W_OUT    52          // output columns per tile
#define TILE_H   32          // output rows per tile
#define ROWS_PT  16          // rows per thread, vertical pass
#define S_PIX    68          // padded pixel stride (conflict-free)
#define SMEM_BYTES (TILE_H * S_PIX * 16)   // 34816 B (pixel = 8 ch fp16 = 16 B)

typedef unsigned long long ull;

// packed f32x2 FMA (Blackwell FFMA2 — only reachable via PTX)
__device__ __forceinline__ ull fma2(ull a, ull b, ull c) {
    ull d;
    asm("fma.rn.f32x2 %0, %1, %2, %3;" : "=l"(d) : "l"(a), "l"(b), "l"(c));
    return d;
}
__device__ __forceinline__ ull pkf2(float lo, float hi) {
    ull d;
    asm("mov.b64 %0, {%1, %2};" : "=l"(d) : "f"(lo), "f"(hi));
    return d;
}
__device__ __forceinline__ float2 upk(ull v) {
    float2 r;
    asm("mov.b64 {%0, %1}, %2;" : "=f"(r.x), "=f"(r.y) : "l"(v));
    return r;
}
__device__ __forceinline__ ull wpair(float w) {   // (w, w) packed — constant-folded
    unsigned u = __float_as_uint(w);
    return ((ull)u << 32) | u;
}

union H2U { __half2 h; unsigned u; };

__global__ __launch_bounds__(256, 3)
void gauss13_kernel(const float* __restrict__ in, float* __restrict__ out)
{
    // Normalized 1D gaussian, sigma=2, ws=13; symmetric -> 7 unique packed regs
    const float W[13] = {
        0.0022181959f, 0.0087731350f, 0.0270231560f, 0.0648251852f,
        0.1211093910f, 0.1762131227f, 0.1996756275f, 0.1762131227f,
        0.1211093910f, 0.0648251852f, 0.0270231560f, 0.0087731350f,
        0.0022181959f };
    ull w2[13];
    #pragma unroll
    for (int k = 0; k < 13; ++k) w2[k] = wpair(W[k]);

    extern __shared__ uint2 sV[];   // [TILE_H][S_PIX][2 cq] half4 (8 B)

    const int z  = blockIdx.z;
    const int n  = z >> 1;
    const int p  = z & 1;            // channel half
    const int x0 = blockIdx.x * W_OUT;
    const int y0 = blockIdx.y * TILE_H;

    const ulonglong2* __restrict__ ibase =
        reinterpret_cast<const ulonglong2*>(in) + (size_t)n * (IMG * IMG * 4) + p * 2;
    float4* __restrict__ obase =
        reinterpret_cast<float4*>(out) + (size_t)n * (IMG * IMG * 4) + p * 2;

    // ---------------- vertical pass (global -> smem fp16), packed ring ----------------
    {
        const int tx  = threadIdx.x;      // 0..127
        const int col = tx >> 1;          // 0..63 incl. halo
        const int cq  = tx & 1;
        const int gw  = x0 - 6 + col;
        const bool wok = ((unsigned)gw < (unsigned)IMG);
        const int r0  = y0 + (int)threadIdx.y * ROWS_PT - 6;
        const ulonglong2* cb = ibase + cq;

        ulonglong2 win[13];
        #pragma unroll
        for (int i = 0; i < 12; ++i) {
            int h = r0 + i;
            win[i] = (wok && (unsigned)h < (unsigned)IMG)
                   ? __ldg(cb + ((size_t)h * IMG + gw) * 4)
                   : make_ulonglong2(0ull, 0ull);
        }
        #pragma unroll
        for (int r = 0; r < ROWS_PT; ++r) {
            int h = r0 + 12 + r;
            win[(r + 12) % 13] = (wok && (unsigned)h < (unsigned)IMG)
                   ? __ldg(cb + ((size_t)h * IMG + gw) * 4)
                   : make_ulonglong2(0ull, 0ull);
            ull a0 = 0ull, a1 = 0ull;
            #pragma unroll
            for (int k = 0; k < 13; ++k) {
                ulonglong2 v = win[(r + k) % 13];
                a0 = fma2(w2[k], v.x, a0);
                a1 = fma2(w2[k], v.y, a1);
            }
            float2 f01 = upk(a0);
            float2 f23 = upk(a1);
            H2U u0, u1;
            u0.h = __floats2half2_rn(f01.x, f01.y);
            u1.h = __floats2half2_rn(f23.x, f23.y);
            uint2 pk; pk.x = u0.u; pk.y = u1.u;
            sV[((threadIdx.y * ROWS_PT + r) * S_PIX + col) * 2 + cq] = pk;
        }
    }
    __syncthreads();

    // ---------------- horizontal pass (smem fp16 -> global f32), packed ----------------
    {
        const int tid  = (int)threadIdx.y * 128 + (int)threadIdx.x;
        const int cq   = tid & 1;
        const int seg  = (tid >> 1) & 3;   // output col = seg + 4*i
        const int hrow = tid >> 3;         // 0..31

        ull acc0[13], acc1[13];
        #pragma unroll
        for (int i = 0; i < 13; ++i) { acc0[i] = 0ull; acc1[i] = 0ull; }

        const uint2* rowp = sV + (hrow * S_PIX) * 2 + cq;

        #pragma unroll
        for (int c = 0; c < 61; ++c) {
            uint2 pk = rowp[(seg + c) * 2];
            H2U u0, u1; u0.u = pk.x; u1.u = pk.y;
            float2 f01 = __half22float2(u0.h);
            float2 f23 = __half22float2(u1.h);
            ull v0 = pkf2(f01.x, f01.y);
            ull v1 = pkf2(f23.x, f23.y);
            #pragma unroll
            for (int i = 0; i < 13; ++i) {
                int k = c - 4 * i;
                if (k >= 0 && k < 13) {     // compile-time pruned (3-4 live i per c)
                    acc0[i] = fma2(w2[k], v0, acc0[i]);
                    acc1[i] = fma2(w2[k], v1, acc1[i]);
                }
            }
        }

        const int gy = y0 + hrow;
        float4* ob = obase + cq;
        #pragma unroll
        for (int i = 0; i < 13; ++i) {
            int gx = x0 + seg + 4 * i;
            if (gx < IMG) {
                float2 a = upk(acc0[i]);
                float2 b = upk(acc1[i]);
                ob[((size_t)gy * IMG + gx) * 4] = make_float4(a.x, a.y, b.x, b.y);
            }
        }
    }
}

extern "C" void kernel_launch(void* const* d_in, const int* in_sizes, int n_in,
                              void* d_out, int out_size)
{
    (void)in_sizes; (void)n_in; (void)out_size;
    const float* x = (const float*)d_in[0];
    float* y = (float*)d_out;

    cudaFuncSetAttribute(gauss13_kernel,
                         cudaFuncAttributeMaxDynamicSharedMemorySize, SMEM_BYTES);

    dim3 grid(8, IMG / TILE_H, 32 * 2);
    dim3 block(128, 2);
    gauss13_kernel<<<grid, block, SMEM_BYTES>>>(x, y);
}

// round 4
// speedup vs baseline: 1.0116x; 1.0116x over previous
#include <cuda_runtime.h>
#include <cuda_fp16.h>

#define IMG      384
#define W_OUT    52          // output columns per tile
#define TILE_H   16          // output rows per tile (one 16-row strip per block)
#define S_PIX    68          // padded pixel stride (conflict-free)
#define SMEM_BYTES (TILE_H * S_PIX * 16)   // 17408 B (pixel = 8 ch fp16 = 16 B)

// Normalized 1D gaussian, sigma=2, ws=13. constexpr at namespace scope ->
// fully-unrolled taps fold to FFMA immediate form (rt_SMSP=1).
__device__ constexpr float GW[13] = {
    0.0022181959f, 0.0087731350f, 0.0270231560f, 0.0648251852f,
    0.1211093910f, 0.1762131227f, 0.1996756275f, 0.1762131227f,
    0.1211093910f, 0.0648251852f, 0.0270231560f, 0.0087731350f,
    0.0022181959f };

__device__ __forceinline__ float4 f4z() { return make_float4(0.f, 0.f, 0.f, 0.f); }

union H2U { __half2 h; unsigned u; };

__global__ __launch_bounds__(128, 7)
void gauss13_kernel(const float* __restrict__ in, float* __restrict__ out)
{
    extern __shared__ uint2 sV[];   // [TILE_H][S_PIX][2 cq] of half4 (8 B)

    const int z  = blockIdx.z;
    const int n  = z >> 1;
    const int p  = z & 1;            // channel half (ch 0-7 / 8-15)
    const int x0 = blockIdx.x * W_OUT;
    const int y0 = blockIdx.y * TILE_H;

    const float4* __restrict__ ibase =
        reinterpret_cast<const float4*>(in) + (size_t)n * (IMG * IMG * 4) + p * 2;
    float4* __restrict__ obase =
        reinterpret_cast<float4*>(out) + (size_t)n * (IMG * IMG * 4) + p * 2;

    // ---------------- vertical pass (global -> smem fp16), register ring ----------------
    {
        const int tx  = threadIdx.x;      // 0..127
        const int col = tx >> 1;          // 0..63 incl. halo
        const int cq  = tx & 1;
        const int gw  = x0 - 6 + col;
        const bool wok = ((unsigned)gw < (unsigned)IMG);
        const int r0  = y0 - 6;           // first loaded row
        const float4* cb = ibase + cq;

        float4 win[13];
        #pragma unroll
        for (int i = 0; i < 12; ++i) {
            int h = r0 + i;
            win[i] = (wok && (unsigned)h < (unsigned)IMG)
                   ? __ldg(cb + ((size_t)h * IMG + gw) * 4) : f4z();
        }
        #pragma unroll
        for (int r = 0; r < TILE_H; ++r) {
            int h = r0 + 12 + r;
            win[(r + 12) % 13] = (wok && (unsigned)h < (unsigned)IMG)
                   ? __ldg(cb + ((size_t)h * IMG + gw) * 4) : f4z();
            float4 a = f4z();
            #pragma unroll
            for (int k = 0; k < 13; ++k) {
                const float4 v = win[(r + k) % 13];
                const float wk = GW[k];      // literal after unroll -> FFMA-imm
                a.x = fmaf(wk, v.x, a.x);
                a.y = fmaf(wk, v.y, a.y);
                a.z = fmaf(wk, v.z, a.z);
                a.w = fmaf(wk, v.w, a.w);
            }
            H2U u0, u1;
            u0.h = __floats2half2_rn(a.x, a.y);
            u1.h = __floats2half2_rn(a.z, a.w);
            uint2 pk; pk.x = u0.u; pk.y = u1.u;
            sV[(r * S_PIX + col) * 2 + cq] = pk;
        }
    }
    __syncthreads();

    // ---------------- horizontal pass (smem fp16 -> global f32) -------------------------
    {
        const int tid  = threadIdx.x;      // 0..127
        const int cq   = tid & 1;
        const int seg  = (tid >> 1) & 3;   // output col = seg + 4*i
        const int hrow = tid >> 3;         // 0..15

        float4 acc[13];
        #pragma unroll
        for (int i = 0; i < 13; ++i) acc[i] = f4z();

        const uint2* rowp = sV + (hrow * S_PIX) * 2 + cq;

        #pragma unroll
        for (int c = 0; c < 61; ++c) {
            uint2 pk = rowp[(seg + c) * 2];
            H2U u0, u1; u0.u = pk.x; u1.u = pk.y;
            float2 f01 = __half22float2(u0.h);
            float2 f23 = __half22float2(u1.h);
            #pragma unroll
            for (int i = 0; i < 13; ++i) {
                const int k = c - 4 * i;
                if (k >= 0 && k < 13) {     // compile-time pruned
                    const float wk = GW[k]; // literal -> FFMA-imm
                    acc[i].x = fmaf(wk, f01.x, acc[i].x);
                    acc[i].y = fmaf(wk, f01.y, acc[i].y);
                    acc[i].z = fmaf(wk, f23.x, acc[i].z);
                    acc[i].w = fmaf(wk, f23.y, acc[i].w);
                }
            }
        }

        const int gy = y0 + hrow;
        float4* ob = obase + cq;
        #pragma unroll
        for (int i = 0; i < 13; ++i) {
            int gx = x0 + seg + 4 * i;
            if (gx < IMG)
                ob[((size_t)gy * IMG + gx) * 4] = acc[i];
        }
    }
}

extern "C" void kernel_launch(void* const* d_in, const int* in_sizes, int n_in,
                              void* d_out, int out_size)
{
    (void)in_sizes; (void)n_in; (void)out_size;
    const float* x = (const float*)d_in[0];
    float* y = (float*)d_out;

    cudaFuncSetAttribute(gauss13_kernel,
                         cudaFuncAttributeMaxDynamicSharedMemorySize, SMEM_BYTES);

    dim3 grid(8 /* ceil(384/52) */, IMG / TILE_H /* 24 */, 32 * 2);
    dim3 block(128);
    gauss13_kernel<<<grid, block, SMEM_BYTES>>>(x, y);
}